// round 12
// baseline (speedup 1.0000x reference)
#include <cuda_runtime.h>
#include <cuda_bf16.h>
#include <math.h>
#include <stdint.h>

#define HH 56
#define WW 56
#define HWSZ 3136
#define NB 8
#define NPTS 65536
#define THREADS 256
#define NCHUNKS 16384          // 524288 points / 32 per warp-chunk

// Precomputed G[b][hw][64] = sum_c feat[b][c][hw] * W1[c][n]  (img half of layer 1)
__device__ float g_G[NB * HWSZ * 64];

extern __shared__ char dsm[];

// ---------------- smem map (decoder), byte offsets ----------------
#define W1FH 0          // [64 n][128 k] bf16 hi, swizzled, 16 chunks/row
#define W1FL 16384
#define W2HS 32768      // [64][64] bf16, 8 chunks/row
#define W2LS 40960
#define W3HS 49152
#define W3LS 57344
#define B1S  65536
#define B2S  65792
#define B3S  66048
#define W4S  66304
#define B4S  66560
#define BGS  66576      // 192 floats = 768B
#define GB_OFF 67360    // per-warp G staging: 8 warps x 32 pts x 68 f32 (cols 64..67 = tap weights)
#define TOS_OFF (GB_OFF + 8 * 32 * 68 * 4)   // per-warp tap offsets: 8 x 32 x 4 ints
#define SMEMB (TOS_OFF + 8 * 32 * 4 * 4)     // 141088

#define LDSM4(R, A) asm volatile("ldmatrix.sync.aligned.m8n8.x4.shared.b16 {%0,%1,%2,%3}, [%4];" \
  : "=r"((R)[0]), "=r"((R)[1]), "=r"((R)[2]), "=r"((R)[3]) : "r"(A))

#define MMA(D, A, B0, B1) asm volatile( \
  "mma.sync.aligned.m16n8k16.row.col.f32.bf16.bf16.f32 {%0,%1,%2,%3}, {%4,%5,%6,%7}, {%8,%9}, {%0,%1,%2,%3};" \
  : "+f"((D)[0]), "+f"((D)[1]), "+f"((D)[2]), "+f"((D)[3]) \
  : "r"((A)[0]), "r"((A)[1]), "r"((A)[2]), "r"((A)[3]), "r"(B0), "r"(B1))

__device__ __forceinline__ void hilo(float a, float b, uint32_t& h, uint32_t& l) {
  __nv_bfloat16 ha = __float2bfloat16(a), hb = __float2bfloat16(b);
  __nv_bfloat162 hp; hp.x = ha; hp.y = hb;
  __nv_bfloat162 lp;
  lp.x = __float2bfloat16(a - __bfloat162float(ha));
  lp.y = __float2bfloat16(b - __bfloat162float(hb));
  h = *(uint32_t*)&hp; l = *(uint32_t*)&lp;
}

// C frags -> next-layer A frags (hi/lo), bias + relu. Verified layout (R7).
__device__ __forceinline__ void build_afr(const float d[8][4], const float* bs, int q,
                                          uint32_t ah[4][4], uint32_t al[4][4]) {
#pragma unroll
  for (int kk = 0; kk < 4; kk++) {
    const int j0 = 2 * kk, j1 = 2 * kk + 1;
    float ba = bs[8*j0+2*q], bb = bs[8*j0+2*q+1];
    float bc = bs[8*j1+2*q], bd = bs[8*j1+2*q+1];
    hilo(fmaxf(d[j0][0]+ba,0.f), fmaxf(d[j0][1]+bb,0.f), ah[kk][0], al[kk][0]);
    hilo(fmaxf(d[j0][2]+ba,0.f), fmaxf(d[j0][3]+bb,0.f), ah[kk][1], al[kk][1]);
    hilo(fmaxf(d[j1][0]+bc,0.f), fmaxf(d[j1][1]+bd,0.f), ah[kk][2], al[kk][2]);
    hilo(fmaxf(d[j1][2]+bc,0.f), fmaxf(d[j1][3]+bd,0.f), ah[kk][3], al[kk][3]);
  }
}

// 64x64 layer for TWO m-tiles. Term-outer MMA ordering: 16 distinct accumulators
// between successive writes to the same register; W frags preloaded per k-step.
__device__ __forceinline__ void layer64x2(float d[2][8][4],
                                          const uint32_t ah[2][4][4], const uint32_t al[2][4][4],
                                          uint32_t sb, uint32_t baseH, uint32_t baseL,
                                          int bnu, int bkb) {
#pragma unroll
  for (int mt = 0; mt < 2; mt++)
#pragma unroll
    for (int j = 0; j < 8; j++)
#pragma unroll
      for (int e = 0; e < 4; e++) d[mt][j][e] = 0.f;
#pragma unroll
  for (int kk = 0; kk < 4; kk++) {
    const int kch = (kk * 16 + bkb) >> 3;
    uint32_t wh[4][4], wl[4][4];
#pragma unroll
    for (int jp = 0; jp < 4; jp++) {
      const int n = jp * 16 + bnu;
      const uint32_t off = (uint32_t)((n << 3) + (kch ^ (n & 7))) * 16u;
      LDSM4(wh[jp], sb + baseH + off);
      LDSM4(wl[jp], sb + baseL + off);
    }
#pragma unroll
    for (int jp = 0; jp < 4; jp++)
#pragma unroll
      for (int mt = 0; mt < 2; mt++) {
        MMA(d[mt][2*jp],   ah[mt][kk], wh[jp][0], wh[jp][1]);
        MMA(d[mt][2*jp+1], ah[mt][kk], wh[jp][2], wh[jp][3]);
      }
#pragma unroll
    for (int jp = 0; jp < 4; jp++)
#pragma unroll
      for (int mt = 0; mt < 2; mt++) {
        MMA(d[mt][2*jp],   al[mt][kk], wh[jp][0], wh[jp][1]);
        MMA(d[mt][2*jp+1], al[mt][kk], wh[jp][2], wh[jp][3]);
      }
#pragma unroll
    for (int jp = 0; jp < 4; jp++)
#pragma unroll
      for (int mt = 0; mt < 2; mt++) {
        MMA(d[mt][2*jp],   ah[mt][kk], wl[jp][0], wl[jp][1]);
        MMA(d[mt][2*jp+1], ah[mt][kk], wl[jp][2], wl[jp][3]);
      }
  }
}

// ---------------------------------------------------------------------------
// Kernel 1: G precompute. grid = 196, block = 256. dyn smem 98304.
// ---------------------------------------------------------------------------
__global__ __launch_bounds__(THREADS, 1)
void g_precomp_kernel(const float* __restrict__ feat, const float* __restrict__ W1) {
  float* fs = (float*)dsm;          // [128 c][128 row]
  float* ws = fs + 128 * 128;       // [128 c][64 n]
  const int tid = threadIdx.x;
  const int R0 = blockIdx.x * 128;
  for (int idx = tid; idx < 128 * 128; idx += THREADS) {
    int c = idx >> 7, i = idx & 127;
    int row = R0 + i, b = row / HWSZ, hw = row - b * HWSZ;
    fs[c * 128 + i] = feat[((size_t)b * 128 + c) * HWSZ + hw];
  }
  for (int idx = tid; idx < 128 * 64; idx += THREADS) ws[idx] = W1[idx];
  __syncthreads();
  const int r0 = (tid >> 3) * 4, c0 = (tid & 7) * 8;
  float acc[4][8];
#pragma unroll
  for (int a = 0; a < 4; a++)
#pragma unroll
    for (int j = 0; j < 8; j++) acc[a][j] = 0.f;
  for (int c = 0; c < 128; c++) {
    float a0 = fs[c*128+r0], a1 = fs[c*128+r0+1], a2 = fs[c*128+r0+2], a3 = fs[c*128+r0+3];
#pragma unroll
    for (int j = 0; j < 8; j++) {
      float w = ws[c*64 + c0 + j];
      acc[0][j] = fmaf(a0, w, acc[0][j]);
      acc[1][j] = fmaf(a1, w, acc[1][j]);
      acc[2][j] = fmaf(a2, w, acc[2][j]);
      acc[3][j] = fmaf(a3, w, acc[3][j]);
    }
  }
#pragma unroll
  for (int a = 0; a < 4; a++) {
    float* dst = g_G + (size_t)(R0 + r0 + a) * 64 + c0;
#pragma unroll
    for (int j = 0; j < 8; j += 4)
      *(float4*)(dst + j) = make_float4(acc[a][j], acc[a][j+1], acc[a][j+2], acc[a][j+3]);
  }
}

// ---------------------------------------------------------------------------
// Kernel 2: persistent decoder — warp-independent, 32 pts per warp-iter.
// ---------------------------------------------------------------------------
__global__ __launch_bounds__(THREADS, 1)
void decoder_kernel(const float* __restrict__ points,
                    const float* __restrict__ kmat,
                    const float* __restrict__ rtm,
                    const float* __restrict__ Bg,
                    const float* __restrict__ W1, const float* __restrict__ b1,
                    const float* __restrict__ W2, const float* __restrict__ b2,
                    const float* __restrict__ W3, const float* __restrict__ b3,
                    const float* __restrict__ W4, const float* __restrict__ b4,
                    float* __restrict__ out)
{
  const int tid = threadIdx.x;
  const uint32_t sb = (uint32_t)__cvta_generic_to_shared(dsm);

  // ---- one-time weight prep (identical layouts to R10, which passed) ----
  for (int i = tid; i < 8192; i += THREADS) {        // W1 fourier half -> [n][k] hi/lo
    int k = i >> 6, n = i & 63;
    float v = W1[(128 + k) * 64 + n];
    __nv_bfloat16 h = __float2bfloat16(v);
    uint32_t off = (uint32_t)((n << 4) + ((k >> 3) ^ (n & 7))) * 16u + (uint32_t)(k & 7) * 2u;
    *(__nv_bfloat16*)(dsm + W1FH + off) = h;
    *(__nv_bfloat16*)(dsm + W1FL + off) = __float2bfloat16(v - __bfloat162float(h));
  }
  for (int i = tid; i < 4096; i += THREADS) {        // W2, W3 -> [n][k] hi/lo
    int k = i >> 6, n = i & 63;
    uint32_t off = (uint32_t)((n << 3) + ((k >> 3) ^ (n & 7))) * 16u + (uint32_t)(k & 7) * 2u;
    float v2 = W2[i];
    __nv_bfloat16 h2 = __float2bfloat16(v2);
    *(__nv_bfloat16*)(dsm + W2HS + off) = h2;
    *(__nv_bfloat16*)(dsm + W2LS + off) = __float2bfloat16(v2 - __bfloat162float(h2));
    float v3 = W3[i];
    __nv_bfloat16 h3 = __float2bfloat16(v3);
    *(__nv_bfloat16*)(dsm + W3HS + off) = h3;
    *(__nv_bfloat16*)(dsm + W3LS + off) = __float2bfloat16(v3 - __bfloat162float(h3));
  }
  if (tid < 64) {
    ((float*)(dsm + B1S))[tid] = b1[tid];
    ((float*)(dsm + B2S))[tid] = b2[tid];
    ((float*)(dsm + B3S))[tid] = b3[tid];
    ((float*)(dsm + W4S))[tid] = W4[tid];
  }
  if (tid == 0) ((float*)(dsm + B4S))[0] = b4[0];
  for (int i = tid; i < 192; i += THREADS)
    ((float*)(dsm + BGS))[i] = Bg[i] * 6.283185307179586f;
  __syncthreads();

  const float* b1s = (const float*)(dsm + B1S);
  const float* b2s = (const float*)(dsm + B2S);
  const float* b3s = (const float*)(dsm + B3S);
  const float* W4s = (const float*)(dsm + W4S);
  const float* Bgs = (const float*)(dsm + BGS);
  const float b4v  = ((const float*)(dsm + B4S))[0];

  const int lane = tid & 31, wrp = tid >> 5;
  const int q = lane & 3, g = lane >> 2;
  const int u = lane & 7, tt = lane >> 3;
  const int bnu = u + ((tt >> 1) & 1) * 8;    // W ldmatrix n sub-offset
  const int bkb = (tt & 1) * 8;               // W ldmatrix k sub-offset
  float* gb = (float*)(dsm + GB_OFF) + wrp * (32 * 68);
  int*  tos = (int*)(dsm + TOS_OFF) + wrp * (32 * 4);

  const int gwarp = blockIdx.x * 8 + wrp;
  const int wstride = gridDim.x * 8;

  for (int chunk = gwarp; chunk < NCHUNKS; chunk += wstride) {
    const int ptg = chunk << 5;
    const int b = ptg >> 16;
    const int nb = ptg & 65535;

    // ---- projection for own point (lane = point) ----
    const float* pp = points + ((size_t)b * NPTS + nb + lane) * 3;
    const float px = pp[0], py = pp[1], pz = pp[2];
    {
      const float* R = rtm + b * 12;
      const float* K = kmat + b * 9;
      float c0v = R[0]*px + R[1]*py + R[2]*pz  + R[3];
      float c1v = R[4]*px + R[5]*py + R[6]*pz  + R[7];
      float c2v = R[8]*px + R[9]*py + R[10]*pz + R[11];
      float i0 = K[0]*c0v + K[1]*c1v + K[2]*c2v;
      float i1 = K[3]*c0v + K[4]*c1v + K[5]*c2v;
      float i2 = K[6]*c0v + K[7]*c1v + K[8]*c2v;
      float zz = i2 + 1e-8f;
      float uu = i0 / zz, vv = i1 / zz;
      float valid = (i2 > 0.0f) ? 1.0f : 0.0f;
      float un = (2.0f*uu + 1.0f) / (float)WW - 1.0f;
      float vn = (2.0f*vv + 1.0f) / (float)HH - 1.0f;
      float x = ((un + 1.0f) * (float)WW - 1.0f) * 0.5f;
      float y = ((vn + 1.0f) * (float)HH - 1.0f) * 0.5f;
      float x0f = floorf(x), y0f = floorf(y);
      float fx = x - x0f, fy = y - y0f;
      int ix0 = (int)x0f, iy0 = (int)y0f, ix1 = ix0 + 1, iy1 = iy0 + 1;
      float* twd = gb + lane * 68 + 64;
      twd[0] = (1.0f-fx)*(1.0f-fy)*valid;
      twd[1] = fx*(1.0f-fy)*valid;
      twd[2] = (1.0f-fx)*fy*valid;
      twd[3] = fx*fy*valid;
      tos[lane*4+0] = (((unsigned)ix0 < WW) && ((unsigned)iy0 < HH)) ? (iy0*WW+ix0) : -1;
      tos[lane*4+1] = (((unsigned)ix1 < WW) && ((unsigned)iy0 < HH)) ? (iy0*WW+ix1) : -1;
      tos[lane*4+2] = (((unsigned)ix0 < WW) && ((unsigned)iy1 < HH)) ? (iy1*WW+ix0) : -1;
      tos[lane*4+3] = (((unsigned)ix1 < WW) && ((unsigned)iy1 < HH)) ? (iy1*WW+ix1) : -1;
    }
    __syncwarp();

    // ---- cooperative coalesced gather: whole warp loads one point-tap row ----
    {
      const float2* Gb2 = (const float2*)(g_G + (size_t)b * HWSZ * 64);
#pragma unroll 4
      for (int pt = 0; pt < 32; pt++) {
        const float* twp = gb + pt * 68 + 64;   // uniform (broadcast) LDS
        const int*   top = tos + pt * 4;
        float ax = 0.f, ay = 0.f;
#pragma unroll
        for (int t = 0; t < 4; t++) {
          int o = top[t];
          if (o >= 0) {
            float2 v = Gb2[(size_t)o * 32 + lane];
            float w = twp[t];
            ax = fmaf(w, v.x, ax);
            ay = fmaf(w, v.y, ay);
          }
        }
        *(float2*)(gb + pt * 68 + 2 * lane) = make_float2(ax, ay);
      }
    }
    __syncwarp();

    // ---- coords of this lane's fragment rows (mt*16 + g, +8) ----
    float rx[4], ry[4], rz[4];
#pragma unroll
    for (int i = 0; i < 4; i++) {
      int r = (i >> 1) * 16 + (i & 1) * 8 + g;
      rx[i] = __shfl_sync(0xFFFFFFFFu, px, r);
      ry[i] = __shfl_sync(0xFFFFFFFFu, py, r);
      rz[i] = __shfl_sync(0xFFFFFFFFu, pz, r);
    }

    // ---- init accumulators from G (f32 img contribution) ----
    float d[2][8][4];
#pragma unroll
    for (int mt = 0; mt < 2; mt++)
#pragma unroll
      for (int j = 0; j < 8; j++) {
        float2 v0 = *(const float2*)(gb + (mt*16 + g) * 68 + 8*j + 2*q);
        float2 v1 = *(const float2*)(gb + (mt*16 + g + 8) * 68 + 8*j + 2*q);
        d[mt][j][0] = v0.x; d[mt][j][1] = v0.y; d[mt][j][2] = v1.x; d[mt][j][3] = v1.y;
      }

    // ---- layer 1 fourier half (K=128): register-built A frags ----
#pragma unroll
    for (int sp = 0; sp < 4; sp++) {
      const int mA = sp * 16 + 2 * q;
      const int mB = mA + 8;
      float g0x = Bgs[3*mA],     g0y = Bgs[3*mA+1],     g0z = Bgs[3*mA+2];
      float g1x = Bgs[3*mA+3],   g1y = Bgs[3*mA+4],     g1z = Bgs[3*mA+5];
      float g2x = Bgs[3*mB],     g2y = Bgs[3*mB+1],     g2z = Bgs[3*mB+2];
      float g3x = Bgs[3*mB+3],   g3y = Bgs[3*mB+4],     g3z = Bgs[3*mB+5];
      uint32_t aS[2][4], aSl[2][4], aC[2][4], aCl[2][4];
#pragma unroll
      for (int mt = 0; mt < 2; mt++) {
#pragma unroll
        for (int rr = 0; rr < 2; rr++) {
          const float X = rx[mt*2+rr], Y = ry[mt*2+rr], Z = rz[mt*2+rr];
          float p0 = X*g0x + Y*g0y + Z*g0z;
          float p1 = X*g1x + Y*g1y + Z*g1z;
          float p2 = X*g2x + Y*g2y + Z*g2z;
          float p3 = X*g3x + Y*g3y + Z*g3z;
          hilo(__sinf(p0), __sinf(p1), aS[mt][rr],   aSl[mt][rr]);
          hilo(__sinf(p2), __sinf(p3), aS[mt][2+rr], aSl[mt][2+rr]);
          hilo(__cosf(p0), __cosf(p1), aC[mt][rr],   aCl[mt][rr]);
          hilo(__cosf(p2), __cosf(p3), aC[mt][2+rr], aCl[mt][2+rr]);
        }
      }
      const int kchS = (sp * 16 + bkb) >> 3;
      const int kchC = (64 + sp * 16 + bkb) >> 3;
      uint32_t wh[4][4], wl[4][4];
      // ---- sin block: preload W frags for all jp, then term-outer MMAs ----
#pragma unroll
      for (int jp = 0; jp < 4; jp++) {
        const int n = jp * 16 + bnu;
        const uint32_t off = (uint32_t)((n << 4) + (kchS ^ (n & 7))) * 16u;
        LDSM4(wh[jp], sb + W1FH + off);
        LDSM4(wl[jp], sb + W1FL + off);
      }
#pragma unroll
      for (int jp = 0; jp < 4; jp++)
#pragma unroll
        for (int mt = 0; mt < 2; mt++) {
          MMA(d[mt][2*jp],   aS[mt], wh[jp][0], wh[jp][1]);
          MMA(d[mt][2*jp+1], aS[mt], wh[jp][2], wh[jp][3]);
        }
#pragma unroll
      for (int jp = 0; jp < 4; jp++)
#pragma unroll
        for (int mt = 0; mt < 2; mt++) {
          MMA(d[mt][2*jp],   aSl[mt], wh[jp][0], wh[jp][1]);
          MMA(d[mt][2*jp+1], aSl[mt], wh[jp][2], wh[jp][3]);
        }
#pragma unroll
      for (int jp = 0; jp < 4; jp++)
#pragma unroll
        for (int mt = 0; mt < 2; mt++) {
          MMA(d[mt][2*jp],   aS[mt], wl[jp][0], wl[jp][1]);
          MMA(d[mt][2*jp+1], aS[mt], wl[jp][2], wl[jp][3]);
        }
      // ---- cos block ----
#pragma unroll
      for (int jp = 0; jp < 4; jp++) {
        const int n = jp * 16 + bnu;
        const uint32_t off = (uint32_t)((n << 4) + (kchC ^ (n & 7))) * 16u;
        LDSM4(wh[jp], sb + W1FH + off);
        LDSM4(wl[jp], sb + W1FL + off);
      }
#pragma unroll
      for (int jp = 0; jp < 4; jp++)
#pragma unroll
        for (int mt = 0; mt < 2; mt++) {
          MMA(d[mt][2*jp],   aC[mt], wh[jp][0], wh[jp][1]);
          MMA(d[mt][2*jp+1], aC[mt], wh[jp][2], wh[jp][3]);
        }
#pragma unroll
      for (int jp = 0; jp < 4; jp++)
#pragma unroll
        for (int mt = 0; mt < 2; mt++) {
          MMA(d[mt][2*jp],   aCl[mt], wh[jp][0], wh[jp][1]);
          MMA(d[mt][2*jp+1], aCl[mt], wh[jp][2], wh[jp][3]);
        }
#pragma unroll
      for (int jp = 0; jp < 4; jp++)
#pragma unroll
        for (int mt = 0; mt < 2; mt++) {
          MMA(d[mt][2*jp],   aC[mt], wl[jp][0], wl[jp][1]);
          MMA(d[mt][2*jp+1], aC[mt], wl[jp][2], wl[jp][3]);
        }
    }

    // ---- layers 2, 3 chained in registers, W shared across both m-tiles ----
    {
      uint32_t ah[2][4][4], al[2][4][4];
      build_afr(d[0], b1s, q, ah[0], al[0]);
      build_afr(d[1], b1s, q, ah[1], al[1]);
      layer64x2(d, ah, al, sb, W2HS, W2LS, bnu, bkb);
      build_afr(d[0], b2s, q, ah[0], al[0]);
      build_afr(d[1], b2s, q, ah[1], al[1]);
      layer64x2(d, ah, al, sb, W3HS, W3LS, bnu, bkb);
    }

    // ---- layer 4 + store ----
#pragma unroll
    for (int mt = 0; mt < 2; mt++) {
      float s0 = 0.f, s1 = 0.f;
#pragma unroll
      for (int j = 0; j < 8; j++) {
        float ba = b3s[8*j+2*q], bb = b3s[8*j+2*q+1];
        float wa = W4s[8*j+2*q], wb = W4s[8*j+2*q+1];
        s0 += fmaxf(d[mt][j][0]+ba, 0.f)*wa + fmaxf(d[mt][j][1]+bb, 0.f)*wb;
        s1 += fmaxf(d[mt][j][2]+ba, 0.f)*wa + fmaxf(d[mt][j][3]+bb, 0.f)*wb;
      }
      s0 += __shfl_xor_sync(0xFFFFFFFFu, s0, 1);
      s0 += __shfl_xor_sync(0xFFFFFFFFu, s0, 2);
      s1 += __shfl_xor_sync(0xFFFFFFFFu, s1, 1);
      s1 += __shfl_xor_sync(0xFFFFFFFFu, s1, 2);
      if (q == 0) {
        out[(size_t)b * NPTS + nb + mt*16 + g]     = s0 + b4v;
        out[(size_t)b * NPTS + nb + mt*16 + g + 8] = s1 + b4v;
      }
    }
    __syncwarp();
  }
}

// ---------------------------------------------------------------------------
extern "C" void kernel_launch(void* const* d_in, const int* in_sizes, int n_in,
                              void* d_out, int out_size) {
  const float* features = (const float*)d_in[0];
  const float* points   = (const float*)d_in[1];
  const float* kmat     = (const float*)d_in[2];
  const float* rtm      = (const float*)d_in[3];
  const float* Bg       = (const float*)d_in[4];
  const float* W1       = (const float*)d_in[5];
  const float* b1       = (const float*)d_in[6];
  const float* W2       = (const float*)d_in[7];
  const float* b2       = (const float*)d_in[8];
  const float* W3       = (const float*)d_in[9];
  const float* b3       = (const float*)d_in[10];
  const float* W4       = (const float*)d_in[11];
  const float* b4       = (const float*)d_in[12];
  float* out            = (float*)d_out;

  cudaFuncSetAttribute(g_precomp_kernel, cudaFuncAttributeMaxDynamicSharedMemorySize, 98304);
  cudaFuncSetAttribute(decoder_kernel,   cudaFuncAttributeMaxDynamicSharedMemorySize, SMEMB);

  g_precomp_kernel<<<196, THREADS, 98304>>>(features, W1);

  int dev = 0, sms = 148;
  cudaGetDevice(&dev);
  cudaDeviceGetAttribute(&sms, cudaDevAttrMultiProcessorCount, dev);
  if (sms <= 0) sms = 148;

  decoder_kernel<<<sms, THREADS, SMEMB>>>(
      points, kmat, rtm, Bg, W1, b1, W2, b2, W3, b3, W4, b4, out);
}

// round 13
// speedup vs baseline: 1.4901x; 1.4901x over previous
#include <cuda_runtime.h>
#include <cuda_bf16.h>
#include <math.h>
#include <stdint.h>

#define HH 56
#define WW 56
#define HWSZ 3136
#define NB 8
#define NPTS 65536
#define THREADS 320
#define NWARPS 10
#define NCHUNKS 16384          // 524288 points / 32 per warp-chunk

// Precomputed G[b][hw][64] = sum_c feat[b][c][hw] * W1[c][n]  (img half of layer 1)
__device__ float g_G[NB * HWSZ * 64];

extern __shared__ char dsm[];

// ---------------- smem map (decoder), byte offsets ----------------
#define W1FH 0          // [64 n][128 k] bf16 hi, swizzled, 16 chunks/row
#define W1FL 16384
#define W2HS 32768      // [64][64] bf16, 8 chunks/row
#define W2LS 40960
#define W3HS 49152
#define W3LS 57344
#define B1S  65536
#define B2S  65792
#define B3S  66048
#define W4S  66304
#define B4S  66560
#define BGS  66576      // 192 floats = 768B
#define GB_OFF 67360    // per-warp G staging: NWARPS x 32 pts x 68 f32
#define SMEMB (GB_OFF + NWARPS * 32 * 68 * 4)   // 154400

#define LDSM4(R, A) asm volatile("ldmatrix.sync.aligned.m8n8.x4.shared.b16 {%0,%1,%2,%3}, [%4];" \
  : "=r"((R)[0]), "=r"((R)[1]), "=r"((R)[2]), "=r"((R)[3]) : "r"(A))

#define MMA(D, A, B0, B1) asm volatile( \
  "mma.sync.aligned.m16n8k16.row.col.f32.bf16.bf16.f32 {%0,%1,%2,%3}, {%4,%5,%6,%7}, {%8,%9}, {%0,%1,%2,%3};" \
  : "+f"((D)[0]), "+f"((D)[1]), "+f"((D)[2]), "+f"((D)[3]) \
  : "r"((A)[0]), "r"((A)[1]), "r"((A)[2]), "r"((A)[3]), "r"(B0), "r"(B1))

__device__ __forceinline__ void hilo(float a, float b, uint32_t& h, uint32_t& l) {
  __nv_bfloat16 ha = __float2bfloat16(a), hb = __float2bfloat16(b);
  __nv_bfloat162 hp; hp.x = ha; hp.y = hb;
  __nv_bfloat162 lp;
  lp.x = __float2bfloat16(a - __bfloat162float(ha));
  lp.y = __float2bfloat16(b - __bfloat162float(hb));
  h = *(uint32_t*)&hp; l = *(uint32_t*)&lp;
}

// C frags -> next-layer A frags (hi/lo), bias + relu. Verified layout (R7).
__device__ __forceinline__ void build_afr(const float d[8][4], const float* bs, int q,
                                          uint32_t ah[4][4], uint32_t al[4][4]) {
#pragma unroll
  for (int kk = 0; kk < 4; kk++) {
    const int j0 = 2 * kk, j1 = 2 * kk + 1;
    float ba = bs[8*j0+2*q], bb = bs[8*j0+2*q+1];
    float bc = bs[8*j1+2*q], bd = bs[8*j1+2*q+1];
    hilo(fmaxf(d[j0][0]+ba,0.f), fmaxf(d[j0][1]+bb,0.f), ah[kk][0], al[kk][0]);
    hilo(fmaxf(d[j0][2]+ba,0.f), fmaxf(d[j0][3]+bb,0.f), ah[kk][1], al[kk][1]);
    hilo(fmaxf(d[j1][0]+bc,0.f), fmaxf(d[j1][1]+bd,0.f), ah[kk][2], al[kk][2]);
    hilo(fmaxf(d[j1][2]+bc,0.f), fmaxf(d[j1][3]+bd,0.f), ah[kk][3], al[kk][3]);
  }
}

// 64x64 layer for TWO m-tiles. Term-outer MMA ordering: 16 distinct accumulators
// between successive writes to the same register; W frags preloaded per k-step.
__device__ __forceinline__ void layer64x2(float d[2][8][4],
                                          const uint32_t ah[2][4][4], const uint32_t al[2][4][4],
                                          uint32_t sb, uint32_t baseH, uint32_t baseL,
                                          int bnu, int bkb) {
#pragma unroll
  for (int mt = 0; mt < 2; mt++)
#pragma unroll
    for (int j = 0; j < 8; j++)
#pragma unroll
      for (int e = 0; e < 4; e++) d[mt][j][e] = 0.f;
#pragma unroll
  for (int kk = 0; kk < 4; kk++) {
    const int kch = (kk * 16 + bkb) >> 3;
    uint32_t wh[4][4], wl[4][4];
#pragma unroll
    for (int jp = 0; jp < 4; jp++) {
      const int n = jp * 16 + bnu;
      const uint32_t off = (uint32_t)((n << 3) + (kch ^ (n & 7))) * 16u;
      LDSM4(wh[jp], sb + baseH + off);
      LDSM4(wl[jp], sb + baseL + off);
    }
#pragma unroll
    for (int jp = 0; jp < 4; jp++)
#pragma unroll
      for (int mt = 0; mt < 2; mt++) {
        MMA(d[mt][2*jp],   ah[mt][kk], wh[jp][0], wh[jp][1]);
        MMA(d[mt][2*jp+1], ah[mt][kk], wh[jp][2], wh[jp][3]);
      }
#pragma unroll
    for (int jp = 0; jp < 4; jp++)
#pragma unroll
      for (int mt = 0; mt < 2; mt++) {
        MMA(d[mt][2*jp],   al[mt][kk], wh[jp][0], wh[jp][1]);
        MMA(d[mt][2*jp+1], al[mt][kk], wh[jp][2], wh[jp][3]);
      }
#pragma unroll
    for (int jp = 0; jp < 4; jp++)
#pragma unroll
      for (int mt = 0; mt < 2; mt++) {
        MMA(d[mt][2*jp],   ah[mt][kk], wl[jp][0], wl[jp][1]);
        MMA(d[mt][2*jp+1], ah[mt][kk], wl[jp][2], wl[jp][3]);
      }
  }
}

// ---------------------------------------------------------------------------
// Kernel 1: G precompute. grid = 196, block = 256. dyn smem 98304.
// ---------------------------------------------------------------------------
__global__ __launch_bounds__(256, 1)
void g_precomp_kernel(const float* __restrict__ feat, const float* __restrict__ W1) {
  float* fs = (float*)dsm;          // [128 c][128 row]
  float* ws = fs + 128 * 128;       // [128 c][64 n]
  const int tid = threadIdx.x;
  const int R0 = blockIdx.x * 128;
  for (int idx = tid; idx < 128 * 128; idx += 256) {
    int c = idx >> 7, i = idx & 127;
    int row = R0 + i, b = row / HWSZ, hw = row - b * HWSZ;
    fs[c * 128 + i] = feat[((size_t)b * 128 + c) * HWSZ + hw];
  }
  for (int idx = tid; idx < 128 * 64; idx += 256) ws[idx] = W1[idx];
  __syncthreads();
  const int r0 = (tid >> 3) * 4, c0 = (tid & 7) * 8;
  float acc[4][8];
#pragma unroll
  for (int a = 0; a < 4; a++)
#pragma unroll
    for (int j = 0; j < 8; j++) acc[a][j] = 0.f;
  for (int c = 0; c < 128; c++) {
    float a0 = fs[c*128+r0], a1 = fs[c*128+r0+1], a2 = fs[c*128+r0+2], a3 = fs[c*128+r0+3];
#pragma unroll
    for (int j = 0; j < 8; j++) {
      float w = ws[c*64 + c0 + j];
      acc[0][j] = fmaf(a0, w, acc[0][j]);
      acc[1][j] = fmaf(a1, w, acc[1][j]);
      acc[2][j] = fmaf(a2, w, acc[2][j]);
      acc[3][j] = fmaf(a3, w, acc[3][j]);
    }
  }
#pragma unroll
  for (int a = 0; a < 4; a++) {
    float* dst = g_G + (size_t)(R0 + r0 + a) * 64 + c0;
#pragma unroll
    for (int j = 0; j < 8; j += 4)
      *(float4*)(dst + j) = make_float4(acc[a][j], acc[a][j+1], acc[a][j+2], acc[a][j+3]);
  }
}

// ---------------------------------------------------------------------------
// Kernel 2: persistent decoder — warp-independent, 32 pts per warp-iter.
// 10 warps/CTA for latency hiding; per-lane gather (max MLP).
// ---------------------------------------------------------------------------
__global__ __launch_bounds__(THREADS, 1)
void decoder_kernel(const float* __restrict__ points,
                    const float* __restrict__ kmat,
                    const float* __restrict__ rtm,
                    const float* __restrict__ Bg,
                    const float* __restrict__ W1, const float* __restrict__ b1,
                    const float* __restrict__ W2, const float* __restrict__ b2,
                    const float* __restrict__ W3, const float* __restrict__ b3,
                    const float* __restrict__ W4, const float* __restrict__ b4,
                    float* __restrict__ out)
{
  const int tid = threadIdx.x;
  const uint32_t sb = (uint32_t)__cvta_generic_to_shared(dsm);

  // ---- one-time weight prep (layouts identical to the 251us kernel) ----
  for (int i = tid; i < 8192; i += THREADS) {        // W1 fourier half -> [n][k] hi/lo
    int k = i >> 6, n = i & 63;
    float v = W1[(128 + k) * 64 + n];
    __nv_bfloat16 h = __float2bfloat16(v);
    uint32_t off = (uint32_t)((n << 4) + ((k >> 3) ^ (n & 7))) * 16u + (uint32_t)(k & 7) * 2u;
    *(__nv_bfloat16*)(dsm + W1FH + off) = h;
    *(__nv_bfloat16*)(dsm + W1FL + off) = __float2bfloat16(v - __bfloat162float(h));
  }
  for (int i = tid; i < 4096; i += THREADS) {        // W2, W3 -> [n][k] hi/lo
    int k = i >> 6, n = i & 63;
    uint32_t off = (uint32_t)((n << 3) + ((k >> 3) ^ (n & 7))) * 16u + (uint32_t)(k & 7) * 2u;
    float v2 = W2[i];
    __nv_bfloat16 h2 = __float2bfloat16(v2);
    *(__nv_bfloat16*)(dsm + W2HS + off) = h2;
    *(__nv_bfloat16*)(dsm + W2LS + off) = __float2bfloat16(v2 - __bfloat162float(h2));
    float v3 = W3[i];
    __nv_bfloat16 h3 = __float2bfloat16(v3);
    *(__nv_bfloat16*)(dsm + W3HS + off) = h3;
    *(__nv_bfloat16*)(dsm + W3LS + off) = __float2bfloat16(v3 - __bfloat162float(h3));
  }
  if (tid < 64) {
    ((float*)(dsm + B1S))[tid] = b1[tid];
    ((float*)(dsm + B2S))[tid] = b2[tid];
    ((float*)(dsm + B3S))[tid] = b3[tid];
    ((float*)(dsm + W4S))[tid] = W4[tid];
  }
  if (tid == 0) ((float*)(dsm + B4S))[0] = b4[0];
  for (int i = tid; i < 192; i += THREADS)
    ((float*)(dsm + BGS))[i] = Bg[i] * 6.283185307179586f;
  __syncthreads();

  const float* b1s = (const float*)(dsm + B1S);
  const float* b2s = (const float*)(dsm + B2S);
  const float* b3s = (const float*)(dsm + B3S);
  const float* W4s = (const float*)(dsm + W4S);
  const float* Bgs = (const float*)(dsm + BGS);
  const float b4v  = ((const float*)(dsm + B4S))[0];

  const int lane = tid & 31, wrp = tid >> 5;
  const int q = lane & 3, g = lane >> 2;
  const int u = lane & 7, tt = lane >> 3;
  const int bnu = u + ((tt >> 1) & 1) * 8;    // W ldmatrix n sub-offset
  const int bkb = (tt & 1) * 8;               // W ldmatrix k sub-offset
  float* gb = (float*)(dsm + GB_OFF) + wrp * (32 * 68);

  const int gwarp = blockIdx.x * NWARPS + wrp;
  const int wstride = gridDim.x * NWARPS;

  for (int chunk = gwarp; chunk < NCHUNKS; chunk += wstride) {
    const int ptg = chunk << 5;
    const int b = ptg >> 16;
    const int nb = ptg & 65535;

    // ---- projection for own point (lane = point) ----
    const float* pp = points + ((size_t)b * NPTS + nb + lane) * 3;
    const float px = pp[0], py = pp[1], pz = pp[2];
    float tw[4]; int to[4];
    {
      const float* R = rtm + b * 12;
      const float* K = kmat + b * 9;
      float c0v = R[0]*px + R[1]*py + R[2]*pz  + R[3];
      float c1v = R[4]*px + R[5]*py + R[6]*pz  + R[7];
      float c2v = R[8]*px + R[9]*py + R[10]*pz + R[11];
      float i0 = K[0]*c0v + K[1]*c1v + K[2]*c2v;
      float i1 = K[3]*c0v + K[4]*c1v + K[5]*c2v;
      float i2 = K[6]*c0v + K[7]*c1v + K[8]*c2v;
      float zz = i2 + 1e-8f;
      float uu = i0 / zz, vv = i1 / zz;
      float valid = (i2 > 0.0f) ? 1.0f : 0.0f;
      float un = (2.0f*uu + 1.0f) / (float)WW - 1.0f;
      float vn = (2.0f*vv + 1.0f) / (float)HH - 1.0f;
      float x = ((un + 1.0f) * (float)WW - 1.0f) * 0.5f;
      float y = ((vn + 1.0f) * (float)HH - 1.0f) * 0.5f;
      float x0f = floorf(x), y0f = floorf(y);
      float fx = x - x0f, fy = y - y0f;
      int ix0 = (int)x0f, iy0 = (int)y0f, ix1 = ix0 + 1, iy1 = iy0 + 1;
      tw[0] = (1.0f-fx)*(1.0f-fy)*valid;
      tw[1] = fx*(1.0f-fy)*valid;
      tw[2] = (1.0f-fx)*fy*valid;
      tw[3] = fx*fy*valid;
      to[0] = (((unsigned)ix0 < WW) && ((unsigned)iy0 < HH)) ? (iy0*WW+ix0) : -1;
      to[1] = (((unsigned)ix1 < WW) && ((unsigned)iy0 < HH)) ? (iy0*WW+ix1) : -1;
      to[2] = (((unsigned)ix0 < WW) && ((unsigned)iy1 < HH)) ? (iy1*WW+ix0) : -1;
      to[3] = (((unsigned)ix1 < WW) && ((unsigned)iy1 < HH)) ? (iy1*WW+ix1) : -1;
    }

    // ---- per-lane gather: lane blends its own point's 64 cols (max MLP) ----
    __syncwarp();
    {
      const float* Gb = g_G + (size_t)b * HWSZ * 64;
#pragma unroll
      for (int half = 0; half < 2; half++) {
        float4 acc[8];
#pragma unroll
        for (int j = 0; j < 8; j++) acc[j] = make_float4(0.f, 0.f, 0.f, 0.f);
#pragma unroll
        for (int t = 0; t < 4; t++) {
          if (to[t] >= 0) {
            const float4* gp = (const float4*)(Gb + (size_t)to[t] * 64 + half * 32);
            const float w = tw[t];
#pragma unroll
            for (int j = 0; j < 8; j++) {
              float4 v = gp[j];
              acc[j].x = fmaf(w, v.x, acc[j].x);
              acc[j].y = fmaf(w, v.y, acc[j].y);
              acc[j].z = fmaf(w, v.z, acc[j].z);
              acc[j].w = fmaf(w, v.w, acc[j].w);
            }
          }
        }
        float* dst = gb + lane * 68 + half * 32;
#pragma unroll
        for (int j = 0; j < 8; j++) *(float4*)(dst + 4*j) = acc[j];
      }
    }
    __syncwarp();

    // ---- coords of this lane's fragment rows (mt*16 + g, +8) ----
    float rx[4], ry[4], rz[4];
#pragma unroll
    for (int i = 0; i < 4; i++) {
      int r = (i >> 1) * 16 + (i & 1) * 8 + g;
      rx[i] = __shfl_sync(0xFFFFFFFFu, px, r);
      ry[i] = __shfl_sync(0xFFFFFFFFu, py, r);
      rz[i] = __shfl_sync(0xFFFFFFFFu, pz, r);
    }

    // ---- init accumulators from G (f32 img contribution) ----
    float d[2][8][4];
#pragma unroll
    for (int mt = 0; mt < 2; mt++)
#pragma unroll
      for (int j = 0; j < 8; j++) {
        float2 v0 = *(const float2*)(gb + (mt*16 + g) * 68 + 8*j + 2*q);
        float2 v1 = *(const float2*)(gb + (mt*16 + g + 8) * 68 + 8*j + 2*q);
        d[mt][j][0] = v0.x; d[mt][j][1] = v0.y; d[mt][j][2] = v1.x; d[mt][j][3] = v1.y;
      }

    // ---- layer 1 fourier half (K=128): register-built A frags ----
#pragma unroll
    for (int sp = 0; sp < 4; sp++) {
      const int mA = sp * 16 + 2 * q;
      const int mB = mA + 8;
      float g0x = Bgs[3*mA],     g0y = Bgs[3*mA+1],     g0z = Bgs[3*mA+2];
      float g1x = Bgs[3*mA+3],   g1y = Bgs[3*mA+4],     g1z = Bgs[3*mA+5];
      float g2x = Bgs[3*mB],     g2y = Bgs[3*mB+1],     g2z = Bgs[3*mB+2];
      float g3x = Bgs[3*mB+3],   g3y = Bgs[3*mB+4],     g3z = Bgs[3*mB+5];
      uint32_t aS[2][4], aSl[2][4], aC[2][4], aCl[2][4];
#pragma unroll
      for (int mt = 0; mt < 2; mt++) {
#pragma unroll
        for (int rr = 0; rr < 2; rr++) {
          const float X = rx[mt*2+rr], Y = ry[mt*2+rr], Z = rz[mt*2+rr];
          float p0 = X*g0x + Y*g0y + Z*g0z;
          float p1 = X*g1x + Y*g1y + Z*g1z;
          float p2 = X*g2x + Y*g2y + Z*g2z;
          float p3 = X*g3x + Y*g3y + Z*g3z;
          hilo(__sinf(p0), __sinf(p1), aS[mt][rr],   aSl[mt][rr]);
          hilo(__sinf(p2), __sinf(p3), aS[mt][2+rr], aSl[mt][2+rr]);
          hilo(__cosf(p0), __cosf(p1), aC[mt][rr],   aCl[mt][rr]);
          hilo(__cosf(p2), __cosf(p3), aC[mt][2+rr], aCl[mt][2+rr]);
        }
      }
      const int kchS = (sp * 16 + bkb) >> 3;
      const int kchC = (64 + sp * 16 + bkb) >> 3;
      uint32_t wh[4][4], wl[4][4];
      // ---- sin block: preload W frags for all jp, then term-outer MMAs ----
#pragma unroll
      for (int jp = 0; jp < 4; jp++) {
        const int n = jp * 16 + bnu;
        const uint32_t off = (uint32_t)((n << 4) + (kchS ^ (n & 7))) * 16u;
        LDSM4(wh[jp], sb + W1FH + off);
        LDSM4(wl[jp], sb + W1FL + off);
      }
#pragma unroll
      for (int jp = 0; jp < 4; jp++)
#pragma unroll
        for (int mt = 0; mt < 2; mt++) {
          MMA(d[mt][2*jp],   aS[mt], wh[jp][0], wh[jp][1]);
          MMA(d[mt][2*jp+1], aS[mt], wh[jp][2], wh[jp][3]);
        }
#pragma unroll
      for (int jp = 0; jp < 4; jp++)
#pragma unroll
        for (int mt = 0; mt < 2; mt++) {
          MMA(d[mt][2*jp],   aSl[mt], wh[jp][0], wh[jp][1]);
          MMA(d[mt][2*jp+1], aSl[mt], wh[jp][2], wh[jp][3]);
        }
#pragma unroll
      for (int jp = 0; jp < 4; jp++)
#pragma unroll
        for (int mt = 0; mt < 2; mt++) {
          MMA(d[mt][2*jp],   aS[mt], wl[jp][0], wl[jp][1]);
          MMA(d[mt][2*jp+1], aS[mt], wl[jp][2], wl[jp][3]);
        }
      // ---- cos block ----
#pragma unroll
      for (int jp = 0; jp < 4; jp++) {
        const int n = jp * 16 + bnu;
        const uint32_t off = (uint32_t)((n << 4) + (kchC ^ (n & 7))) * 16u;
        LDSM4(wh[jp], sb + W1FH + off);
        LDSM4(wl[jp], sb + W1FL + off);
      }
#pragma unroll
      for (int jp = 0; jp < 4; jp++)
#pragma unroll
        for (int mt = 0; mt < 2; mt++) {
          MMA(d[mt][2*jp],   aC[mt], wh[jp][0], wh[jp][1]);
          MMA(d[mt][2*jp+1], aC[mt], wh[jp][2], wh[jp][3]);
        }
#pragma unroll
      for (int jp = 0; jp < 4; jp++)
#pragma unroll
        for (int mt = 0; mt < 2; mt++) {
          MMA(d[mt][2*jp],   aCl[mt], wh[jp][0], wh[jp][1]);
          MMA(d[mt][2*jp+1], aCl[mt], wh[jp][2], wh[jp][3]);
        }
#pragma unroll
      for (int jp = 0; jp < 4; jp++)
#pragma unroll
        for (int mt = 0; mt < 2; mt++) {
          MMA(d[mt][2*jp],   aC[mt], wl[jp][0], wl[jp][1]);
          MMA(d[mt][2*jp+1], aC[mt], wl[jp][2], wl[jp][3]);
        }
    }

    // ---- layers 2, 3 chained in registers, W shared across both m-tiles ----
    {
      uint32_t ah[2][4][4], al[2][4][4];
      build_afr(d[0], b1s, q, ah[0], al[0]);
      build_afr(d[1], b1s, q, ah[1], al[1]);
      layer64x2(d, ah, al, sb, W2HS, W2LS, bnu, bkb);
      build_afr(d[0], b2s, q, ah[0], al[0]);
      build_afr(d[1], b2s, q, ah[1], al[1]);
      layer64x2(d, ah, al, sb, W3HS, W3LS, bnu, bkb);
    }

    // ---- layer 4 + store ----
#pragma unroll
    for (int mt = 0; mt < 2; mt++) {
      float s0 = 0.f, s1 = 0.f;
#pragma unroll
      for (int j = 0; j < 8; j++) {
        float ba = b3s[8*j+2*q], bb = b3s[8*j+2*q+1];
        float wa = W4s[8*j+2*q], wb = W4s[8*j+2*q+1];
        s0 += fmaxf(d[mt][j][0]+ba, 0.f)*wa + fmaxf(d[mt][j][1]+bb, 0.f)*wb;
        s1 += fmaxf(d[mt][j][2]+ba, 0.f)*wa + fmaxf(d[mt][j][3]+bb, 0.f)*wb;
      }
      s0 += __shfl_xor_sync(0xFFFFFFFFu, s0, 1);
      s0 += __shfl_xor_sync(0xFFFFFFFFu, s0, 2);
      s1 += __shfl_xor_sync(0xFFFFFFFFu, s1, 1);
      s1 += __shfl_xor_sync(0xFFFFFFFFu, s1, 2);
      if (q == 0) {
        out[(size_t)b * NPTS + nb + mt*16 + g]     = s0 + b4v;
        out[(size_t)b * NPTS + nb + mt*16 + g + 8] = s1 + b4v;
      }
    }
    __syncwarp();
  }
}

// ---------------------------------------------------------------------------
extern "C" void kernel_launch(void* const* d_in, const int* in_sizes, int n_in,
                              void* d_out, int out_size) {
  const float* features = (const float*)d_in[0];
  const float* points   = (const float*)d_in[1];
  const float* kmat     = (const float*)d_in[2];
  const float* rtm      = (const float*)d_in[3];
  const float* Bg       = (const float*)d_in[4];
  const float* W1       = (const float*)d_in[5];
  const float* b1       = (const float*)d_in[6];
  const float* W2       = (const float*)d_in[7];
  const float* b2       = (const float*)d_in[8];
  const float* W3       = (const float*)d_in[9];
  const float* b3       = (const float*)d_in[10];
  const float* W4       = (const float*)d_in[11];
  const float* b4       = (const float*)d_in[12];
  float* out            = (float*)d_out;

  cudaFuncSetAttribute(g_precomp_kernel, cudaFuncAttributeMaxDynamicSharedMemorySize, 98304);
  cudaFuncSetAttribute(decoder_kernel,   cudaFuncAttributeMaxDynamicSharedMemorySize, SMEMB);

  g_precomp_kernel<<<196, 256, 98304>>>(features, W1);

  int dev = 0, sms = 148;
  cudaGetDevice(&dev);
  cudaDeviceGetAttribute(&sms, cudaDevAttrMultiProcessorCount, dev);
  if (sms <= 0) sms = 148;

  decoder_kernel<<<sms, THREADS, SMEMB>>>(
      points, kmat, rtm, Bg, W1, b1, W2, b2, W3, b3, W4, b4, out);
}